// round 10
// baseline (speedup 1.0000x reference)
#include <cuda_runtime.h>

// BlockLinear: y[b, o] = sum_{k<16} x[b, o*16+k] * w[o, k]
// B=8192, OUT=2048, BLOCK=16.
//
// R9: pinned at service-time floor (~6.92 TB/s, 87% DRAM-active).
// R10: Blackwell 256-bit loads (ld.global.v8.f32 -> LDG.E.256): halves x LDG
// count, and each lane owns a contiguous 8-float half-output so the shuffle
// reduction collapses 8 shfl/row -> 2. Same coalescing, same L2::256B policy.

#define OUT_FEATURES 2048
#define B_ROWS 8192
#define G 16                        // batch rows per warp tile
#define BDIM 256
#define WARPS_PER_BLK (BDIM / 32)
#define O_TILES (OUT_FEATURES / 32)          // 64
#define NBLOCKS ((B_ROWS / G) * O_TILES / WARPS_PER_BLK)   // 4096

struct f8 { float a0,a1,a2,a3,a4,a5,a6,a7; };

__device__ __forceinline__ f8 ldcs_v8(const float* p) {
    f8 v;
    asm volatile("ld.global.cs.L2::256B.v8.f32 {%0,%1,%2,%3,%4,%5,%6,%7}, [%8];"
                 : "=f"(v.a0), "=f"(v.a1), "=f"(v.a2), "=f"(v.a3),
                   "=f"(v.a4), "=f"(v.a5), "=f"(v.a6), "=f"(v.a7)
                 : "l"(p));
    return v;
}

__device__ __forceinline__ float dot8(const f8& x, const float4& wa, const float4& wb) {
    float s0 = x.a0 * wa.x + x.a1 * wa.y + x.a2 * wa.z + x.a3 * wa.w;
    float s1 = x.a4 * wb.x + x.a5 * wb.y + x.a6 * wb.z + x.a7 * wb.w;
    return s0 + s1;
}

__global__ __launch_bounds__(BDIM, 5) void block_linear_kernel(
    const float* __restrict__ x,     // x as float
    const float4* __restrict__ w4,   // weight as float4: w4[o*4 + chunk]
    float* __restrict__ out)
{
    const int lane = threadIdx.x & 31;
    const int w    = blockIdx.x * WARPS_PER_BLK + (threadIdx.x >> 5);
    const int o_tile = (w & (O_TILES - 1)) << 5;   // 32 consecutive outputs
    const int b0     = (w >> 6) << 4;              // 16 consecutive batch rows

    const int h  = lane & 1;    // which 8-float half of the output
    const int oq = lane >> 1;   // output-within-16 group

    // Lane i, load j covers half h of output (o_tile + j*16 + oq).
    // Weight float4s: w4[o*4 + h*2 + {0,1}] — contiguous across lanes.
    const float4 w0a = __ldg(&w4[(o_tile +  0 + oq) * 4 + h * 2 + 0]);
    const float4 w0b = __ldg(&w4[(o_tile +  0 + oq) * 4 + h * 2 + 1]);
    const float4 w1a = __ldg(&w4[(o_tile + 16 + oq) * 4 + h * 2 + 0]);
    const float4 w1b = __ldg(&w4[(o_tile + 16 + oq) * 4 + h * 2 + 1]);

    // Store target: lane i -> output (i&1)*16 + (i>>1); bijective over the
    // 32-output tile, one contiguous 128B line per warp.
    const int o_store = o_tile + h * 16 + oq;

    #pragma unroll
    for (int g = 0; g < G; g++) {
        const int b = b0 + g;
        const long long base_f = (long long)b * 32768 + (long long)o_tile * 16;

        // Two 1KB-contiguous warp loads cover the 2KB row tile.
        const f8 xv0 = ldcs_v8(x + base_f +   0 + lane * 8);
        const f8 xv1 = ldcs_v8(x + base_f + 256 + lane * 8);

        float p0 = dot8(xv0, w0a, w0b);   // half h of output o_tile + oq
        float p1 = dot8(xv1, w1a, w1b);   // half h of output o_tile + 16 + oq

        // Combine the two halves (lanes 2k, 2k+1).
        p0 += __shfl_xor_sync(0xFFFFFFFFu, p0, 1);
        p1 += __shfl_xor_sync(0xFFFFFFFFu, p1, 1);

        __stcs(&out[(long long)b * OUT_FEATURES + o_store], h ? p1 : p0);
    }
}

extern "C" void kernel_launch(void* const* d_in, const int* in_sizes, int n_in,
                              void* d_out, int out_size)
{
    const float* xf = (const float*)d_in[0];
    const float4* w4 = (const float4*)d_in[1];
    float* out = (float*)d_out;

    block_linear_kernel<<<NBLOCKS, BDIM>>>(xf, w4, out);
}

// round 11
// speedup vs baseline: 1.0037x; 1.0037x over previous
#include <cuda_runtime.h>

// BlockLinear: y[b, o] = sum_{k<16} x[b, o*16+k] * w[o, k]
// B=8192, OUT=2048, BLOCK=16.
//
// R10: v8 (LDG.E.256) loads -> best delivered BW (6.965 TB/s, 87.9% DRAM),
// L1 22%, issue 10%. Remaining lever: in-flight load capacity per SM.
// R11: occupancy 5 -> 6 blocks/SM (regs capped 42, 75% occ) for +20% MLP,
// and fold .nc into the v8 streaming load. Otherwise identical to R10.

#define OUT_FEATURES 2048
#define B_ROWS 8192
#define G 16                        // batch rows per warp tile
#define BDIM 256
#define WARPS_PER_BLK (BDIM / 32)
#define O_TILES (OUT_FEATURES / 32)          // 64
#define NBLOCKS ((B_ROWS / G) * O_TILES / WARPS_PER_BLK)   // 4096

struct f8 { float a0,a1,a2,a3,a4,a5,a6,a7; };

__device__ __forceinline__ f8 ldcs_v8(const float* p) {
    f8 v;
    asm volatile("ld.global.nc.cs.L2::256B.v8.f32 {%0,%1,%2,%3,%4,%5,%6,%7}, [%8];"
                 : "=f"(v.a0), "=f"(v.a1), "=f"(v.a2), "=f"(v.a3),
                   "=f"(v.a4), "=f"(v.a5), "=f"(v.a6), "=f"(v.a7)
                 : "l"(p));
    return v;
}

__device__ __forceinline__ float dot8(const f8& x, const float4& wa, const float4& wb) {
    float s0 = x.a0 * wa.x + x.a1 * wa.y + x.a2 * wa.z + x.a3 * wa.w;
    float s1 = x.a4 * wb.x + x.a5 * wb.y + x.a6 * wb.z + x.a7 * wb.w;
    return s0 + s1;
}

__global__ __launch_bounds__(BDIM, 6) void block_linear_kernel(
    const float* __restrict__ x,     // x as float
    const float4* __restrict__ w4,   // weight as float4: w4[o*4 + chunk]
    float* __restrict__ out)
{
    const int lane = threadIdx.x & 31;
    const int w    = blockIdx.x * WARPS_PER_BLK + (threadIdx.x >> 5);
    const int o_tile = (w & (O_TILES - 1)) << 5;   // 32 consecutive outputs
    const int b0     = (w >> 6) << 4;              // 16 consecutive batch rows

    const int h  = lane & 1;    // which 8-float half of the output
    const int oq = lane >> 1;   // output-within-16 group

    // Lane i, load j covers half h of output (o_tile + j*16 + oq).
    const float4 w0a = __ldg(&w4[(o_tile +  0 + oq) * 4 + h * 2 + 0]);
    const float4 w0b = __ldg(&w4[(o_tile +  0 + oq) * 4 + h * 2 + 1]);
    const float4 w1a = __ldg(&w4[(o_tile + 16 + oq) * 4 + h * 2 + 0]);
    const float4 w1b = __ldg(&w4[(o_tile + 16 + oq) * 4 + h * 2 + 1]);

    // Store target: lane i -> output (i&1)*16 + (i>>1); bijective over the
    // 32-output tile, one contiguous 128B line per warp.
    const int o_store = o_tile + h * 16 + oq;

    #pragma unroll
    for (int g = 0; g < G; g++) {
        const int b = b0 + g;
        const long long base_f = (long long)b * 32768 + (long long)o_tile * 16;

        // Two 1KB-contiguous warp loads cover the 2KB row tile.
        const f8 xv0 = ldcs_v8(x + base_f +   0 + lane * 8);
        const f8 xv1 = ldcs_v8(x + base_f + 256 + lane * 8);

        float p0 = dot8(xv0, w0a, w0b);   // half h of output o_tile + oq
        float p1 = dot8(xv1, w1a, w1b);   // half h of output o_tile + 16 + oq

        // Combine the two halves (lanes 2k, 2k+1).
        p0 += __shfl_xor_sync(0xFFFFFFFFu, p0, 1);
        p1 += __shfl_xor_sync(0xFFFFFFFFu, p1, 1);

        __stcs(&out[(long long)b * OUT_FEATURES + o_store], h ? p1 : p0);
    }
}

extern "C" void kernel_launch(void* const* d_in, const int* in_sizes, int n_in,
                              void* d_out, int out_size)
{
    const float* xf = (const float*)d_in[0];
    const float4* w4 = (const float4*)d_in[1];
    float* out = (float*)d_out;

    block_linear_kernel<<<NBLOCKS, BDIM>>>(xf, w4, out);
}

// round 12
// speedup vs baseline: 1.0136x; 1.0099x over previous
#include <cuda_runtime.h>

// BlockLinear: y[b, o] = sum_{k<16} x[b, o*16+k] * w[o, k]
// B=8192, OUT=2048, BLOCK=16.
//
// FINAL (R12 = R9 verbatim). Six rounds of evidence: all kernel shapes pin at
// ~6.9-7.0 TB/s (87-88% DRAM-active) with wall time == traffic/BW exactly.
// This is the GB300 memory-system ceiling for a 94%-read fp32 stream; traffic
// is irreducible. Banking the best-measured configuration:
//   - transposed warp tile: perfectly coalesced 512B warp loads
//   - ld.global.nc.cs.L2::256B on x (evict-first, 256B fetch granularity)
//   - weights register-pinned per 16-row tile (L2-resident reloads)
//   - shfl_xor chunk reduction, one contiguous 128B store line per warp

#define OUT_FEATURES 2048
#define B_ROWS 8192
#define G 16                        // batch rows per warp tile
#define BDIM 256
#define WARPS_PER_BLK (BDIM / 32)
#define O_TILES (OUT_FEATURES / 32)          // 64
#define NBLOCKS ((B_ROWS / G) * O_TILES / WARPS_PER_BLK)   // 4096

__device__ __forceinline__ float4 ldnc_cs_256B(const float4* p) {
    float4 v;
    asm volatile("ld.global.nc.cs.L2::256B.v4.f32 {%0,%1,%2,%3}, [%4];"
                 : "=f"(v.x), "=f"(v.y), "=f"(v.z), "=f"(v.w)
                 : "l"(p));
    return v;
}

__global__ __launch_bounds__(BDIM, 5) void block_linear_kernel(
    const float4* __restrict__ x4,   // x as float4
    const float4* __restrict__ w4,   // weight as float4: w4[o*4 + c]
    float* __restrict__ out)
{
    const int lane = threadIdx.x & 31;
    const int w    = blockIdx.x * WARPS_PER_BLK + (threadIdx.x >> 5);
    const int o_tile = (w & (O_TILES - 1)) << 5;   // 32 consecutive outputs
    const int b0     = (w >> 6) << 4;              // 16 consecutive batch rows

    const int c = lane & 3;    // chunk index within an output (4 float4 = 16 floats)
    const int r = lane >> 2;   // row-within-8 group

    // Weights for this warp's 32 outputs, distributed across lanes (L2-resident).
    const float4 wv0 = __ldg(&w4[(o_tile + 0 * 8 + r) * 4 + c]);
    const float4 wv1 = __ldg(&w4[(o_tile + 1 * 8 + r) * 4 + c]);
    const float4 wv2 = __ldg(&w4[(o_tile + 2 * 8 + r) * 4 + c]);
    const float4 wv3 = __ldg(&w4[(o_tile + 3 * 8 + r) * 4 + c]);

    #pragma unroll
    for (int g = 0; g < G; g++) {
        const int b = b0 + g;
        const long long xbase = ((long long)b * OUT_FEATURES + o_tile) << 2;

        // Perfectly coalesced: 512B contiguous per warp-load, 256B L2 lines,
        // non-coherent read-only path, evict-first.
        const float4 xv0 = ldnc_cs_256B(&x4[xbase + 0 * 32 + lane]);
        const float4 xv1 = ldnc_cs_256B(&x4[xbase + 1 * 32 + lane]);
        const float4 xv2 = ldnc_cs_256B(&x4[xbase + 2 * 32 + lane]);
        const float4 xv3 = ldnc_cs_256B(&x4[xbase + 3 * 32 + lane]);

        float p0 = xv0.x * wv0.x + xv0.y * wv0.y + xv0.z * wv0.z + xv0.w * wv0.w;
        float p1 = xv1.x * wv1.x + xv1.y * wv1.y + xv1.z * wv1.z + xv1.w * wv1.w;
        float p2 = xv2.x * wv2.x + xv2.y * wv2.y + xv2.z * wv2.z + xv2.w * wv2.w;
        float p3 = xv3.x * wv3.x + xv3.y * wv3.y + xv3.z * wv3.z + xv3.w * wv3.w;

        // Reduce the 4 chunk-lanes of each output.
        p0 += __shfl_xor_sync(0xFFFFFFFFu, p0, 1);
        p1 += __shfl_xor_sync(0xFFFFFFFFu, p1, 1);
        p2 += __shfl_xor_sync(0xFFFFFFFFu, p2, 1);
        p3 += __shfl_xor_sync(0xFFFFFFFFu, p3, 1);
        p0 += __shfl_xor_sync(0xFFFFFFFFu, p0, 2);
        p1 += __shfl_xor_sync(0xFFFFFFFFu, p1, 2);
        p2 += __shfl_xor_sync(0xFFFFFFFFu, p2, 2);
        p3 += __shfl_xor_sync(0xFFFFFFFFu, p3, 2);

        // Lane i stores output (i%4)*8 + i/4 — bijective over the 32-output
        // tile, one contiguous 128B line per warp.
        const float v = (c == 0) ? p0 : (c == 1) ? p1 : (c == 2) ? p2 : p3;
        __stcs(&out[(long long)b * OUT_FEATURES + o_tile + c * 8 + r], v);
    }
}

extern "C" void kernel_launch(void* const* d_in, const int* in_sizes, int n_in,
                              void* d_out, int out_size)
{
    const float4* x4 = (const float4*)d_in[0];
    const float4* w4 = (const float4*)d_in[1];
    float* out = (float*)d_out;

    block_linear_kernel<<<NBLOCKS, BDIM>>>(x4, w4, out);
}